// round 16
// baseline (speedup 1.0000x reference)
#include <cuda_runtime.h>
#include <cuda_bf16.h>
#include <cuda_fp16.h>
#include <cstdint>
#include <cstddef>

// Problem constants
constexpr int B_  = 2;
constexpr int S_  = 2048;
constexpr int H_  = 1024;
constexpr int NH_ = 16;
constexpr int HD_ = 64;
constexpr int M_  = B_ * S_;   // 4096

// Fixed-max softmax constants (exp2 domain)
constexpr float L2E_ = 1.4426950408889634f;
constexpr float M2_  = 8.0f * L2E_;

// Scratch (allocation-free: __device__ globals)
__device__ float g_maskf[B_ * S_];    // -M2_ (keep) or -1e30 (masked)
__device__ __half g_hq[(size_t)M_ * H_];
__device__ __half g_hk[(size_t)M_ * H_];
__device__ __half g_hv[(size_t)M_ * H_];
__device__ __half g_hwq[(size_t)H_ * H_];
__device__ __half g_hwk[(size_t)H_ * H_];
__device__ __half g_hwv[(size_t)H_ * H_];
__device__ __half g_hwo[(size_t)H_ * H_];
__device__ __half g_qh[(size_t)M_ * H_];
__device__ __half g_kh[(size_t)M_ * H_];
__device__ __half g_vh[(size_t)M_ * H_];
__device__ __half g_ch[(size_t)M_ * H_];

// ---------------------------------------------------------------------------
// Warp-MMA helpers (portable ISA, plain sm_103 target)
// ---------------------------------------------------------------------------
__device__ __forceinline__ uint32_t smem_to_u32(const void* p) {
    uint32_t a;
    asm("{ .reg .u64 t; cvta.to.shared.u64 t, %1; cvt.u32.u64 %0, t; }"
        : "=r"(a) : "l"(p));
    return a;
}
__device__ __forceinline__ void ldsm_x4(uint32_t r[4], uint32_t a) {
    asm volatile("ldmatrix.sync.aligned.m8n8.x4.shared.b16 {%0,%1,%2,%3}, [%4];"
                 : "=r"(r[0]), "=r"(r[1]), "=r"(r[2]), "=r"(r[3]) : "r"(a));
}
__device__ __forceinline__ void ldsm_x4_trans(uint32_t r[4], uint32_t a) {
    asm volatile("ldmatrix.sync.aligned.m8n8.x4.trans.shared.b16 {%0,%1,%2,%3}, [%4];"
                 : "=r"(r[0]), "=r"(r[1]), "=r"(r[2]), "=r"(r[3]) : "r"(a));
}
__device__ __forceinline__ void mma_f16(float c[4], const uint32_t a[4],
                                        const uint32_t b[2]) {
    asm volatile(
        "mma.sync.aligned.m16n8k16.row.col.f32.f16.f16.f32 "
        "{%0,%1,%2,%3}, {%4,%5,%6,%7}, {%8,%9}, {%0,%1,%2,%3};"
        : "+f"(c[0]), "+f"(c[1]), "+f"(c[2]), "+f"(c[3])
        : "r"(a[0]), "r"(a[1]), "r"(a[2]), "r"(a[3]), "r"(b[0]), "r"(b[1]));
}
__device__ __forceinline__ float ex2f(float x) {
    float r;
    asm("ex2.approx.ftz.f32 %0, %1;" : "=f"(r) : "f"(x));
    return r;
}
__device__ __forceinline__ void cp_async16(uint32_t saddr, const void* gptr) {
    asm volatile("cp.async.cg.shared.global [%0], [%1], 16;"
                 :: "r"(saddr), "l"(gptr));
}
#define CP_COMMIT() asm volatile("cp.async.commit_group;" ::: "memory")
#define CP_WAIT1()  asm volatile("cp.async.wait_group 1;" ::: "memory")
#define CP_WAIT0()  asm volatile("cp.async.wait_group 0;" ::: "memory")

// ---------------------------------------------------------------------------
// Mask normalization: -M2_ (keep) / -1e30 (masked)
// ---------------------------------------------------------------------------
__global__ void mask_normalize(const unsigned int* __restrict__ w)
{
    __shared__ unsigned int flags;
    const int tid = threadIdx.x;
    if (tid == 0) flags = 0u;
    __syncthreads();
    const unsigned int x = w[tid];
    unsigned int f = 0u;
    if (x != 0u && x != 1u && x != 0x3F800000u) f |= 1u;
    if (x == 0x3F800000u) f |= 2u;
    if (f) atomicOr(&flags, f);
    __syncthreads();
    const int byte_mode = (flags & 1u) ? 1 : 0;
    if (byte_mode) {
        const unsigned char* b8 = (const unsigned char*)w;
        for (int i = tid; i < B_ * S_; i += 1024)
            g_maskf[i] = (b8[i] != 0) ? -1e30f : -M2_;
    } else {
        for (int i = tid; i < B_ * S_; i += 1024)
            g_maskf[i] = (w[i] != 0u) ? -1e30f : -M2_;
    }
}

// ---------------------------------------------------------------------------
// Convert all GEMM operands fp32 -> f16 (single launch).
// ---------------------------------------------------------------------------
__global__ __launch_bounds__(256) void convert_all(
    const float* __restrict__ q, const float* __restrict__ k,
    const float* __restrict__ v, const float* __restrict__ wq,
    const float* __restrict__ wk, const float* __restrict__ wv,
    const float* __restrict__ wo)
{
    const int blk = blockIdx.x;
    const float* src;
    __half* dst;
    int base;
    if (blk < 4096)        { src = q;  dst = g_hq;  base = blk; }
    else if (blk < 8192)   { src = k;  dst = g_hk;  base = blk - 4096; }
    else if (blk < 12288)  { src = v;  dst = g_hv;  base = blk - 8192; }
    else if (blk < 13312)  { src = wq; dst = g_hwq; base = blk - 12288; }
    else if (blk < 14336)  { src = wk; dst = g_hwk; base = blk - 13312; }
    else if (blk < 15360)  { src = wv; dst = g_hwv; base = blk - 14336; }
    else                   { src = wo; dst = g_hwo; base = blk - 15360; }

    const int i = (base * 256 + threadIdx.x) * 4;
    const float4 x = *(const float4*)&src[i];
    uint2 o;
    __half2 lo = __floats2half2_rn(x.x, x.y);
    __half2 hi = __floats2half2_rn(x.z, x.w);
    o.x = *(uint32_t*)&lo;
    o.y = *(uint32_t*)&hi;
    *(uint2*)&dst[i] = o;
}

// ---------------------------------------------------------------------------
// Shared GEMM body (NT): C[M,N] = A[M,K] @ W[N,K]^T + bias (fp32 accum)
// 128x128 CTA tile, BK=64, 8 warps (2x4), 3-stage cp.async, 1 sync/stage.
// ---------------------------------------------------------------------------
constexpr int GSTRB  = 144;                   // bytes per smem row
constexpr int GTILEB = 128 * GSTRB;           // 18432 B per tile
constexpr int GBUFB  = 2 * GTILEB;            // A + W per stage (36864)
constexpr int GEMM_SMEM = 3 * GBUFB;          // 110592 B

__device__ __forceinline__ void gemm_body(
    const __half* __restrict__ A, const __half* __restrict__ W,
    const float* __restrict__ bias, float* __restrict__ C,
    __half* __restrict__ Of, int mode, float scale, int K,
    char* smem, int m0, int n0)
{
    const uint32_t smem_u = smem_to_u32(smem);
    const int tid  = threadIdx.x;
    const int wid  = tid >> 5;
    const int lane = tid & 31;
    const int warp_m = wid >> 2;
    const int warp_n = wid & 3;

    float c[4][4][4];
    #pragma unroll
    for (int i = 0; i < 4; i++)
        #pragma unroll
        for (int j = 0; j < 4; j++)
            #pragma unroll
            for (int r = 0; r < 4; r++) c[i][j][r] = 0.0f;

    const int NS = K / 64;   // 16 stages

    auto issue_stage = [&](int s, int buf) {
        const int k0 = s * 64;
        const uint32_t base = smem_u + buf * GBUFB;
        #pragma unroll
        for (int t = 0; t < 8; t++) {
            const int idx = t * 256 + tid;
            const int tile = idx >> 10;            // 0=A, 1=W
            const int within = idx & 1023;
            const int row = within >> 3;
            const int ch = within & 7;
            const __half* src = tile ? (W + (size_t)(n0 + row) * K)
                                     : (A + (size_t)(m0 + row) * K);
            cp_async16(base + tile * GTILEB + row * GSTRB + ch * 16,
                       src + k0 + ch * 8);
        }
    };

    issue_stage(0, 0); CP_COMMIT();
    issue_stage(1, 1); CP_COMMIT();

    const uint32_t a_rowoff  = (uint32_t)(lane & 15) * GSTRB;
    const uint32_t a_koff    = (uint32_t)(lane >> 4) * 16;
    const uint32_t b4_rowoff = (uint32_t)(((lane >> 4) & 1) * 8 + (lane & 7)) * GSTRB;
    const uint32_t b4_koff   = (uint32_t)((lane >> 3) & 1) * 16;

    for (int s = 0; s < NS; s++) {
        if (s < NS - 1) { CP_WAIT1(); } else { CP_WAIT0(); }
        __syncthreads();
        if (s + 2 < NS) {
            issue_stage(s + 2, (s + 2) % 3);
            CP_COMMIT();
        }

        const uint32_t base = smem_u + (s % 3) * GBUFB;
        const uint32_t sA = base;
        const uint32_t sW = base + GTILEB;

        #pragma unroll
        for (int ks = 0; ks < 4; ks++) {
            const uint32_t kb = ks * 32;           // 16 halfs = 32 B
            uint32_t a[4][4], bb[2][4];
            #pragma unroll
            for (int i = 0; i < 4; i++)
                ldsm_x4(a[i], sA + (warp_m * 64 + i * 16) * GSTRB +
                              a_rowoff + kb + a_koff);
            #pragma unroll
            for (int jj = 0; jj < 2; jj++)
                ldsm_x4(bb[jj], sW + (warp_n * 32 + jj * 16) * GSTRB +
                                b4_rowoff + kb + b4_koff);
            #pragma unroll
            for (int i = 0; i < 4; i++)
                #pragma unroll
                for (int jj = 0; jj < 2; jj++) {
                    mma_f16(c[i][2 * jj],     a[i], &bb[jj][0]);
                    mma_f16(c[i][2 * jj + 1], a[i], &bb[jj][2]);
                }
        }
    }

    const int trow = lane >> 2;
    const int tcol = (lane & 3) * 2;
    #pragma unroll
    for (int i = 0; i < 4; i++) {
        const int r0 = m0 + warp_m * 64 + i * 16 + trow;
        #pragma unroll
        for (int j = 0; j < 4; j++) {
            const int cc = n0 + warp_n * 32 + j * 8 + tcol;
            const float b0 = bias[cc];
            const float b1 = bias[cc + 1];
            const float v00 = (c[i][j][0] + b0) * scale;
            const float v01 = (c[i][j][1] + b1) * scale;
            const float v10 = (c[i][j][2] + b0) * scale;
            const float v11 = (c[i][j][3] + b1) * scale;
            const size_t p0 = (size_t)r0 * 1024 + cc;
            const size_t p1 = (size_t)(r0 + 8) * 1024 + cc;
            if (mode == 0) {
                *(float2*)&C[p0] = make_float2(v00, v01);
                *(float2*)&C[p1] = make_float2(v10, v11);
            } else {
                *(__half2*)&Of[p0] = __floats2half2_rn(v00, v01);
                *(__half2*)&Of[p1] = __floats2half2_rn(v10, v11);
            }
        }
    }
}

// Fused Q/K/V projections: grid (8, 32, 3); z selects operand set.
__global__ __launch_bounds__(256, 2) void gemm_qkv(
    const float* __restrict__ qb, const float* __restrict__ kb,
    const float* __restrict__ vb)
{
    extern __shared__ char smem[];
    const int z = blockIdx.z;
    const __half* A = (z == 0) ? g_hq  : (z == 1) ? g_hk  : g_hv;
    const __half* W = (z == 0) ? g_hwq : (z == 1) ? g_hwk : g_hwv;
    __half*      Of = (z == 0) ? g_qh  : (z == 1) ? g_kh  : g_vh;
    const float* bs = (z == 0) ? qb    : (z == 1) ? kb    : vb;
    const float  sc = (z == 0) ? (0.125f * L2E_) : 1.0f;
    gemm_body(A, W, bs, nullptr, Of, 2, sc, H_, smem,
              blockIdx.y * 128, blockIdx.x * 128);
}

// Output projection: ctx f16 @ Wo^T -> fp32 out
__global__ __launch_bounds__(256, 2) void gemm_oproj(
    const float* __restrict__ ob, float* __restrict__ out)
{
    extern __shared__ char smem[];
    gemm_body(g_ch, g_hwo, ob, out, nullptr, 0, 1.0f, H_, smem,
              blockIdx.y * 128, blockIdx.x * 128);
}

// ---------------------------------------------------------------------------
// FP16 FlashAttention, fixed-max softmax (exp2 domain).
// l computed via ones-operand MMA on the same fp16 P used in P·V.
// BQ=128, BK=64, 8 warps, 256 thr, 2 CTAs/SM. Grid (B, NH, S/128).
// ---------------------------------------------------------------------------
constexpr int ASTRB = 144;
constexpr int QTILE = 128 * ASTRB;        // 18432 B
constexpr int KTILE = 64 * ASTRB;
constexpr int VTILE = 64 * ASTRB;
constexpr int KVBUF = KTILE + VTILE;      // 18432 B
constexpr int SQ  = 0;
constexpr int SKV = QTILE;
constexpr int ATTN_SMEM = QTILE + 3 * KVBUF;   // 73728 B

__global__ __launch_bounds__(256, 2) void attn_f16(
    const __half* __restrict__ qh, const __half* __restrict__ kh,
    const __half* __restrict__ vh, const float* __restrict__ maskf,
    const float* __restrict__ bias, __half* __restrict__ ctxo)
{
    extern __shared__ char smem[];
    const uint32_t su = smem_to_u32(smem);
    const int tid = threadIdx.x;
    const int wid = tid >> 5;
    const int lane = tid & 31;
    const int g = lane >> 2;
    const int tig = lane & 3;
    const int b  = blockIdx.x;
    const int h  = blockIdx.y;
    const int q0 = blockIdx.z * 128;

    auto issue_kv = [&](int kt, int buf) {
        const int k0 = kt * 64;
        const uint32_t kbase = su + SKV + buf * KVBUF;
        #pragma unroll
        for (int t = 0; t < 4; t++) {
            const int idx = t * 256 + tid;
            const int tile = idx >> 9;             // 0=K, 1=V
            const int within = idx & 511;
            const int row = within >> 3;
            const int ch = within & 7;
            const __half* src = (tile ? vh : kh) +
                ((size_t)(b * S_ + k0 + row)) * H_ + h * HD_ + ch * 8;
            cp_async16(kbase + tile * KTILE + row * ASTRB + ch * 16, src);
        }
    };

    issue_kv(0, 0); CP_COMMIT();
    issue_kv(1, 1); CP_COMMIT();

    // Stage Q (f16 raw copy): 128 rows x 8 chunks = 1024, 4/thread
    #pragma unroll
    for (int t = 0; t < 4; t++) {
        const int idx = t * 256 + tid;
        const int row = idx >> 3;
        const int ch = idx & 7;
        *(uint4*)(smem + SQ + row * ASTRB + ch * 16) =
            *(const uint4*)
            &qh[((size_t)(b * S_ + q0 + row)) * H_ + h * HD_ + ch * 8];
    }

    float ctx[8][4];
    #pragma unroll
    for (int j = 0; j < 8; j++)
        #pragma unroll
        for (int r = 0; r < 4; r++) ctx[j][r] = 0.0f;
    // Row-sum accumulator via ones-MMA: cl[0]=rowsum(g), cl[2]=rowsum(g+8)
    float cl[4] = {0.0f, 0.0f, 0.0f, 0.0f};
    const uint32_t bones[2] = {0x3C003C00u, 0x3C003C00u};  // f16 ones

    const uint32_t a_rowoff  = (uint32_t)(wid * 16 + (lane & 15)) * ASTRB;
    const uint32_t a_koff    = (uint32_t)(lane >> 4) * 16;
    const uint32_t b4_rowoff = (uint32_t)(((lane >> 4) & 1) * 8 + (lane & 7)) * ASTRB;
    const uint32_t b4_koff   = (uint32_t)((lane >> 3) & 1) * 16;
    const uint32_t v4_rowoff = (uint32_t)(lane & 15) * ASTRB;
    const uint32_t v4_coloff = (uint32_t)((lane >> 4) & 1) * 16;

    const int qg0 = q0 + wid * 16 + g;
    const size_t bias_row0 = ((size_t)h * S_ + qg0) * S_ + 2 * tig;
    const size_t bias_row1 = bias_row0 + 8 * S_;

    constexpr int NT = S_ / 64;   // 32
    for (int kt = 0; kt < NT; kt++) {
        const int k0 = kt * 64;
        if (kt < NT - 1) { CP_WAIT1(); } else { CP_WAIT0(); }
        __syncthreads();
        if (kt + 2 < NT) {
            issue_kv(kt + 2, (kt + 2) % 3);
            CP_COMMIT();
        }

        const uint32_t sk = su + SKV + (kt % 3) * KVBUF;
        const uint32_t sv = sk + KTILE;

        // ---- S = Q'·K^T (f16, fp32 accum); K tiles pairwise via x4 ----
        float c[8][4];
        #pragma unroll
        for (int j = 0; j < 8; j++)
            #pragma unroll
            for (int r = 0; r < 4; r++) c[j][r] = 0.0f;

        #pragma unroll
        for (int ks = 0; ks < 4; ks++) {
            const uint32_t kb = ks * 32;
            uint32_t aq[4];
            ldsm_x4(aq, su + SQ + a_rowoff + kb + a_koff);
            #pragma unroll
            for (int jj = 0; jj < 4; jj++) {
                uint32_t bk4[4];
                ldsm_x4(bk4, sk + (uint32_t)(jj * 16) * ASTRB +
                             b4_rowoff + kb + b4_koff);
                mma_f16(c[2 * jj],     aq, &bk4[0]);
                mma_f16(c[2 * jj + 1], aq, &bk4[2]);
            }
        }

        // ---- P = ex2(c + bias*L2E + maskoff); fixed-max, no rescale ----
        uint32_t ap[4][4];
        #pragma unroll
        for (int j = 0; j < 8; j++) {
            const float2 mk = __ldcs((const float2*)&maskf[b * S_ + k0 + j * 8 + 2 * tig]);
            const float2 b0 = __ldcs((const float2*)&bias[bias_row0 + k0 + j * 8]);
            const float2 b1 = __ldcs((const float2*)&bias[bias_row1 + k0 + j * 8]);
            c[j][0] = ex2f(fmaf(b0.x, L2E_, c[j][0]) + mk.x);
            c[j][1] = ex2f(fmaf(b0.y, L2E_, c[j][1]) + mk.y);
            c[j][2] = ex2f(fmaf(b1.x, L2E_, c[j][2]) + mk.x);
            c[j][3] = ex2f(fmaf(b1.y, L2E_, c[j][3]) + mk.y);
        }

        #pragma unroll
        for (int t = 0; t < 4; t++) {
            __half2 h0 = __floats2half2_rn(c[2 * t][0], c[2 * t][1]);
            __half2 h1 = __floats2half2_rn(c[2 * t][2], c[2 * t][3]);
            __half2 h2 = __floats2half2_rn(c[2 * t + 1][0], c[2 * t + 1][1]);
            __half2 h3 = __floats2half2_rn(c[2 * t + 1][2], c[2 * t + 1][3]);
            ap[t][0] = *(uint32_t*)&h0;
            ap[t][1] = *(uint32_t*)&h1;
            ap[t][2] = *(uint32_t*)&h2;
            ap[t][3] = *(uint32_t*)&h3;
        }

        // ---- ctx += P·V; l += P·1 (ones-operand MMA, exact fp32) ----
        #pragma unroll
        for (int t = 0; t < 4; t++) {
            const uint32_t vbase = sv + (uint32_t)(t * 16) * ASTRB +
                                   v4_rowoff + v4_coloff;
            #pragma unroll
            for (int jd = 0; jd < 8; jd += 2) {
                uint32_t bv4[4];
                ldsm_x4_trans(bv4, vbase + jd * 16);
                mma_f16(ctx[jd],     ap[t], &bv4[0]);
                mma_f16(ctx[jd + 1], ap[t], &bv4[2]);
            }
            mma_f16(cl, ap[t], bones);
        }
    }

    // cl[0]/cl[2] are row sums, identical across the quad (all ones cols).
    const float inv0 = 1.0f / fmaxf(cl[0], 1e-30f);
    const float inv1 = 1.0f / fmaxf(cl[2], 1e-30f);

    const size_t orow0 = ((size_t)(b * S_ + qg0)) * H_ + h * HD_ + 2 * tig;
    const size_t orow1 = orow0 + 8 * H_;
    #pragma unroll
    for (int jd = 0; jd < 8; jd++) {
        *(__half2*)&ctxo[orow0 + jd * 8] =
            __floats2half2_rn(ctx[jd][0] * inv0, ctx[jd][1] * inv0);
        *(__half2*)&ctxo[orow1 + jd * 8] =
            __floats2half2_rn(ctx[jd][2] * inv1, ctx[jd][3] * inv1);
    }
}

// ---------------------------------------------------------------------------
// Launch
// ---------------------------------------------------------------------------
extern "C" void kernel_launch(void* const* d_in, const int* in_sizes, int n_in,
                              void* d_out, int out_size)
{
    (void)in_sizes; (void)n_in; (void)out_size;

    const float* query = (const float*)d_in[0];
    const float* key_t = (const float*)d_in[1];
    const float* value = (const float*)d_in[2];
    const unsigned int* kpm_raw = (const unsigned int*)d_in[3];
    const float* bias  = (const float*)d_in[4];
    const float* q_w = (const float*)d_in[5];
    const float* q_b = (const float*)d_in[6];
    const float* k_w = (const float*)d_in[7];
    const float* k_b = (const float*)d_in[8];
    const float* v_w = (const float*)d_in[9];
    const float* v_b = (const float*)d_in[10];
    const float* o_w = (const float*)d_in[11];
    const float* o_b = (const float*)d_in[12];
    float* out = (float*)d_out;

    float* gmaskf;
    __half *gqh, *gkh, *gvh, *gch;
    cudaGetSymbolAddress((void**)&gmaskf, g_maskf);
    cudaGetSymbolAddress((void**)&gqh, g_qh);
    cudaGetSymbolAddress((void**)&gkh, g_kh);
    cudaGetSymbolAddress((void**)&gvh, g_vh);
    cudaGetSymbolAddress((void**)&gch, g_ch);

    cudaFuncSetAttribute(gemm_qkv,
                         cudaFuncAttributeMaxDynamicSharedMemorySize, GEMM_SMEM);
    cudaFuncSetAttribute(gemm_oproj,
                         cudaFuncAttributeMaxDynamicSharedMemorySize, GEMM_SMEM);
    cudaFuncSetAttribute(attn_f16,
                         cudaFuncAttributeMaxDynamicSharedMemorySize, ATTN_SMEM);

    mask_normalize<<<1, 1024>>>(kpm_raw);
    convert_all<<<16384, 256>>>(query, key_t, value, q_w, k_w, v_w, o_w);

    // Fused Q/K/V projections: grid (8, 32, 3)
    gemm_qkv<<<dim3(H_ / 128, M_ / 128, 3), 256, GEMM_SMEM>>>(q_b, k_b, v_b);

    // Grid (B, NH, S/128): batch pairs adjacent -> bias read hits L2 on 2nd
    attn_f16<<<dim3(B_, NH_, S_ / 128), 256, ATTN_SMEM>>>(
        gqh, gkh, gvh, gmaskf, bias, gch);

    // Output projection (ctx f16 from attention epilogue) -> fp32 out
    gemm_oproj<<<dim3(H_ / 128, M_ / 128), 256, GEMM_SMEM>>>(o_b, out);
}

// round 17
// speedup vs baseline: 1.5188x; 1.5188x over previous
#include <cuda_runtime.h>
#include <cuda_bf16.h>
#include <cuda_fp16.h>
#include <cstdint>
#include <cstddef>

// Problem constants
constexpr int B_  = 2;
constexpr int S_  = 2048;
constexpr int H_  = 1024;
constexpr int NH_ = 16;
constexpr int HD_ = 64;
constexpr int M_  = B_ * S_;   // 4096

// Fixed-max softmax constants (exp2 domain)
constexpr float L2E_ = 1.4426950408889634f;
constexpr float M2_  = 8.0f * L2E_;

// Scratch (allocation-free: __device__ globals)
__device__ float g_maskf[B_ * S_];    // -M2_ (keep) or -1e30 (masked)
__device__ __half g_hq[(size_t)M_ * H_];
__device__ __half g_hk[(size_t)M_ * H_];
__device__ __half g_hv[(size_t)M_ * H_];
__device__ __half g_hwq[(size_t)H_ * H_];
__device__ __half g_hwk[(size_t)H_ * H_];
__device__ __half g_hwv[(size_t)H_ * H_];
__device__ __half g_hwo[(size_t)H_ * H_];
__device__ __half g_qh[(size_t)M_ * H_];
__device__ __half g_kh[(size_t)M_ * H_];
__device__ __half g_vh[(size_t)M_ * H_];
__device__ __half g_ch[(size_t)M_ * H_];

// ---------------------------------------------------------------------------
// Warp-MMA helpers (portable ISA, plain sm_103 target)
// ---------------------------------------------------------------------------
__device__ __forceinline__ uint32_t smem_to_u32(const void* p) {
    uint32_t a;
    asm("{ .reg .u64 t; cvta.to.shared.u64 t, %1; cvt.u32.u64 %0, t; }"
        : "=r"(a) : "l"(p));
    return a;
}
__device__ __forceinline__ void ldsm_x4(uint32_t r[4], uint32_t a) {
    asm volatile("ldmatrix.sync.aligned.m8n8.x4.shared.b16 {%0,%1,%2,%3}, [%4];"
                 : "=r"(r[0]), "=r"(r[1]), "=r"(r[2]), "=r"(r[3]) : "r"(a));
}
__device__ __forceinline__ void ldsm_x4_trans(uint32_t r[4], uint32_t a) {
    asm volatile("ldmatrix.sync.aligned.m8n8.x4.trans.shared.b16 {%0,%1,%2,%3}, [%4];"
                 : "=r"(r[0]), "=r"(r[1]), "=r"(r[2]), "=r"(r[3]) : "r"(a));
}
__device__ __forceinline__ void mma_f16(float c[4], const uint32_t a[4],
                                        const uint32_t b[2]) {
    asm volatile(
        "mma.sync.aligned.m16n8k16.row.col.f32.f16.f16.f32 "
        "{%0,%1,%2,%3}, {%4,%5,%6,%7}, {%8,%9}, {%0,%1,%2,%3};"
        : "+f"(c[0]), "+f"(c[1]), "+f"(c[2]), "+f"(c[3])
        : "r"(a[0]), "r"(a[1]), "r"(a[2]), "r"(a[3]), "r"(b[0]), "r"(b[1]));
}
__device__ __forceinline__ float ex2f(float x) {
    float r;
    asm("ex2.approx.ftz.f32 %0, %1;" : "=f"(r) : "f"(x));
    return r;
}
__device__ __forceinline__ void cp_async16(uint32_t saddr, const void* gptr) {
    asm volatile("cp.async.cg.shared.global [%0], [%1], 16;"
                 :: "r"(saddr), "l"(gptr));
}
#define CP_COMMIT() asm volatile("cp.async.commit_group;" ::: "memory")
#define CP_WAIT1()  asm volatile("cp.async.wait_group 1;" ::: "memory")
#define CP_WAIT0()  asm volatile("cp.async.wait_group 0;" ::: "memory")

// ---------------------------------------------------------------------------
// Mask normalization: -M2_ (keep) / -1e30 (masked)
// ---------------------------------------------------------------------------
__global__ void mask_normalize(const unsigned int* __restrict__ w)
{
    __shared__ unsigned int flags;
    const int tid = threadIdx.x;
    if (tid == 0) flags = 0u;
    __syncthreads();
    const unsigned int x = w[tid];
    unsigned int f = 0u;
    if (x != 0u && x != 1u && x != 0x3F800000u) f |= 1u;
    if (x == 0x3F800000u) f |= 2u;
    if (f) atomicOr(&flags, f);
    __syncthreads();
    const int byte_mode = (flags & 1u) ? 1 : 0;
    if (byte_mode) {
        const unsigned char* b8 = (const unsigned char*)w;
        for (int i = tid; i < B_ * S_; i += 1024)
            g_maskf[i] = (b8[i] != 0) ? -1e30f : -M2_;
    } else {
        for (int i = tid; i < B_ * S_; i += 1024)
            g_maskf[i] = (w[i] != 0u) ? -1e30f : -M2_;
    }
}

// ---------------------------------------------------------------------------
// Convert all GEMM operands fp32 -> f16 (single launch).
// ---------------------------------------------------------------------------
__global__ __launch_bounds__(256) void convert_all(
    const float* __restrict__ q, const float* __restrict__ k,
    const float* __restrict__ v, const float* __restrict__ wq,
    const float* __restrict__ wk, const float* __restrict__ wv,
    const float* __restrict__ wo)
{
    const int blk = blockIdx.x;
    const float* src;
    __half* dst;
    int base;
    if (blk < 4096)        { src = q;  dst = g_hq;  base = blk; }
    else if (blk < 8192)   { src = k;  dst = g_hk;  base = blk - 4096; }
    else if (blk < 12288)  { src = v;  dst = g_hv;  base = blk - 8192; }
    else if (blk < 13312)  { src = wq; dst = g_hwq; base = blk - 12288; }
    else if (blk < 14336)  { src = wk; dst = g_hwk; base = blk - 13312; }
    else if (blk < 15360)  { src = wv; dst = g_hwv; base = blk - 14336; }
    else                   { src = wo; dst = g_hwo; base = blk - 15360; }

    const int i = (base * 256 + threadIdx.x) * 4;
    const float4 x = *(const float4*)&src[i];
    uint2 o;
    __half2 lo = __floats2half2_rn(x.x, x.y);
    __half2 hi = __floats2half2_rn(x.z, x.w);
    o.x = *(uint32_t*)&lo;
    o.y = *(uint32_t*)&hi;
    *(uint2*)&dst[i] = o;
}

// ---------------------------------------------------------------------------
// Shared GEMM body (NT): C[M,N] = A[M,K] @ W[N,K]^T + bias (fp32 accum)
// 128x128 CTA tile, BK=64, 8 warps (2x4), 3-stage cp.async, 1 sync/stage.
// ---------------------------------------------------------------------------
constexpr int GSTRB  = 144;                   // bytes per smem row
constexpr int GTILEB = 128 * GSTRB;           // 18432 B per tile
constexpr int GBUFB  = 2 * GTILEB;            // A + W per stage (36864)
constexpr int GEMM_SMEM = 3 * GBUFB;          // 110592 B

__device__ __forceinline__ void gemm_body(
    const __half* __restrict__ A, const __half* __restrict__ W,
    const float* __restrict__ bias, float* __restrict__ C,
    __half* __restrict__ Of, int mode, float scale, int K,
    char* smem, int m0, int n0)
{
    const uint32_t smem_u = smem_to_u32(smem);
    const int tid  = threadIdx.x;
    const int wid  = tid >> 5;
    const int lane = tid & 31;
    const int warp_m = wid >> 2;
    const int warp_n = wid & 3;

    float c[4][4][4];
    #pragma unroll
    for (int i = 0; i < 4; i++)
        #pragma unroll
        for (int j = 0; j < 4; j++)
            #pragma unroll
            for (int r = 0; r < 4; r++) c[i][j][r] = 0.0f;

    const int NS = K / 64;   // 16 stages

    auto issue_stage = [&](int s, int buf) {
        const int k0 = s * 64;
        const uint32_t base = smem_u + buf * GBUFB;
        #pragma unroll
        for (int t = 0; t < 8; t++) {
            const int idx = t * 256 + tid;
            const int tile = idx >> 10;            // 0=A, 1=W
            const int within = idx & 1023;
            const int row = within >> 3;
            const int ch = within & 7;
            const __half* src = tile ? (W + (size_t)(n0 + row) * K)
                                     : (A + (size_t)(m0 + row) * K);
            cp_async16(base + tile * GTILEB + row * GSTRB + ch * 16,
                       src + k0 + ch * 8);
        }
    };

    issue_stage(0, 0); CP_COMMIT();
    issue_stage(1, 1); CP_COMMIT();

    const uint32_t a_rowoff  = (uint32_t)(lane & 15) * GSTRB;
    const uint32_t a_koff    = (uint32_t)(lane >> 4) * 16;
    const uint32_t b4_rowoff = (uint32_t)(((lane >> 4) & 1) * 8 + (lane & 7)) * GSTRB;
    const uint32_t b4_koff   = (uint32_t)((lane >> 3) & 1) * 16;

    for (int s = 0; s < NS; s++) {
        if (s < NS - 1) { CP_WAIT1(); } else { CP_WAIT0(); }
        __syncthreads();
        if (s + 2 < NS) {
            issue_stage(s + 2, (s + 2) % 3);
            CP_COMMIT();
        }

        const uint32_t base = smem_u + (s % 3) * GBUFB;
        const uint32_t sA = base;
        const uint32_t sW = base + GTILEB;

        #pragma unroll
        for (int ks = 0; ks < 4; ks++) {
            const uint32_t kb = ks * 32;           // 16 halfs = 32 B
            uint32_t a[4][4], bb[2][4];
            #pragma unroll
            for (int i = 0; i < 4; i++)
                ldsm_x4(a[i], sA + (warp_m * 64 + i * 16) * GSTRB +
                              a_rowoff + kb + a_koff);
            #pragma unroll
            for (int jj = 0; jj < 2; jj++)
                ldsm_x4(bb[jj], sW + (warp_n * 32 + jj * 16) * GSTRB +
                                b4_rowoff + kb + b4_koff);
            #pragma unroll
            for (int i = 0; i < 4; i++)
                #pragma unroll
                for (int jj = 0; jj < 2; jj++) {
                    mma_f16(c[i][2 * jj],     a[i], &bb[jj][0]);
                    mma_f16(c[i][2 * jj + 1], a[i], &bb[jj][2]);
                }
        }
    }

    const int trow = lane >> 2;
    const int tcol = (lane & 3) * 2;
    #pragma unroll
    for (int i = 0; i < 4; i++) {
        const int r0 = m0 + warp_m * 64 + i * 16 + trow;
        #pragma unroll
        for (int j = 0; j < 4; j++) {
            const int cc = n0 + warp_n * 32 + j * 8 + tcol;
            const float b0 = bias[cc];
            const float b1 = bias[cc + 1];
            const float v00 = (c[i][j][0] + b0) * scale;
            const float v01 = (c[i][j][1] + b1) * scale;
            const float v10 = (c[i][j][2] + b0) * scale;
            const float v11 = (c[i][j][3] + b1) * scale;
            const size_t p0 = (size_t)r0 * 1024 + cc;
            const size_t p1 = (size_t)(r0 + 8) * 1024 + cc;
            if (mode == 0) {
                *(float2*)&C[p0] = make_float2(v00, v01);
                *(float2*)&C[p1] = make_float2(v10, v11);
            } else {
                *(__half2*)&Of[p0] = __floats2half2_rn(v00, v01);
                *(__half2*)&Of[p1] = __floats2half2_rn(v10, v11);
            }
        }
    }
}

// Fused Q/K/V projections: grid (8, 32, 3); z selects operand set.
__global__ __launch_bounds__(256, 2) void gemm_qkv(
    const float* __restrict__ qb, const float* __restrict__ kb,
    const float* __restrict__ vb)
{
    extern __shared__ char smem[];
    const int z = blockIdx.z;
    const __half* A = (z == 0) ? g_hq  : (z == 1) ? g_hk  : g_hv;
    const __half* W = (z == 0) ? g_hwq : (z == 1) ? g_hwk : g_hwv;
    __half*      Of = (z == 0) ? g_qh  : (z == 1) ? g_kh  : g_vh;
    const float* bs = (z == 0) ? qb    : (z == 1) ? kb    : vb;
    const float  sc = (z == 0) ? (0.125f * L2E_) : 1.0f;
    gemm_body(A, W, bs, nullptr, Of, 2, sc, H_, smem,
              blockIdx.y * 128, blockIdx.x * 128);
}

// Output projection: ctx f16 @ Wo^T -> fp32 out
__global__ __launch_bounds__(256, 2) void gemm_oproj(
    const float* __restrict__ ob, float* __restrict__ out)
{
    extern __shared__ char smem[];
    gemm_body(g_ch, g_hwo, ob, out, nullptr, 0, 1.0f, H_, smem,
              blockIdx.y * 128, blockIdx.x * 128);
}

// ---------------------------------------------------------------------------
// FP16 FlashAttention, fixed-max softmax (exp2 domain).
// l via ones-operand MMA; plain cached loads for bias/mask (L2 reuse).
// BQ=128, BK=64, 8 warps, 256 thr, 2 CTAs/SM. Grid (B, NH, S/128).
// ---------------------------------------------------------------------------
constexpr int ASTRB = 144;
constexpr int QTILE = 128 * ASTRB;        // 18432 B
constexpr int KTILE = 64 * ASTRB;
constexpr int VTILE = 64 * ASTRB;
constexpr int KVBUF = KTILE + VTILE;      // 18432 B
constexpr int SQ  = 0;
constexpr int SKV = QTILE;
constexpr int ATTN_SMEM = QTILE + 3 * KVBUF;   // 73728 B

__global__ __launch_bounds__(256, 2) void attn_f16(
    const __half* __restrict__ qh, const __half* __restrict__ kh,
    const __half* __restrict__ vh, const float* __restrict__ maskf,
    const float* __restrict__ bias, __half* __restrict__ ctxo)
{
    extern __shared__ char smem[];
    const uint32_t su = smem_to_u32(smem);
    const int tid = threadIdx.x;
    const int wid = tid >> 5;
    const int lane = tid & 31;
    const int g = lane >> 2;
    const int tig = lane & 3;
    const int b  = blockIdx.x;
    const int h  = blockIdx.y;
    const int q0 = blockIdx.z * 128;

    auto issue_kv = [&](int kt, int buf) {
        const int k0 = kt * 64;
        const uint32_t kbase = su + SKV + buf * KVBUF;
        #pragma unroll
        for (int t = 0; t < 4; t++) {
            const int idx = t * 256 + tid;
            const int tile = idx >> 9;             // 0=K, 1=V
            const int within = idx & 511;
            const int row = within >> 3;
            const int ch = within & 7;
            const __half* src = (tile ? vh : kh) +
                ((size_t)(b * S_ + k0 + row)) * H_ + h * HD_ + ch * 8;
            cp_async16(kbase + tile * KTILE + row * ASTRB + ch * 16, src);
        }
    };

    issue_kv(0, 0); CP_COMMIT();
    issue_kv(1, 1); CP_COMMIT();

    // Stage Q (f16 raw copy): 128 rows x 8 chunks = 1024, 4/thread
    #pragma unroll
    for (int t = 0; t < 4; t++) {
        const int idx = t * 256 + tid;
        const int row = idx >> 3;
        const int ch = idx & 7;
        *(uint4*)(smem + SQ + row * ASTRB + ch * 16) =
            *(const uint4*)
            &qh[((size_t)(b * S_ + q0 + row)) * H_ + h * HD_ + ch * 8];
    }

    float ctx[8][4];
    #pragma unroll
    for (int j = 0; j < 8; j++)
        #pragma unroll
        for (int r = 0; r < 4; r++) ctx[j][r] = 0.0f;
    // Row-sum accumulator via ones-MMA: cl[0]=rowsum(g), cl[2]=rowsum(g+8)
    float cl[4] = {0.0f, 0.0f, 0.0f, 0.0f};
    const uint32_t bones[2] = {0x3C003C00u, 0x3C003C00u};  // f16 ones

    const uint32_t a_rowoff  = (uint32_t)(wid * 16 + (lane & 15)) * ASTRB;
    const uint32_t a_koff    = (uint32_t)(lane >> 4) * 16;
    const uint32_t b4_rowoff = (uint32_t)(((lane >> 4) & 1) * 8 + (lane & 7)) * ASTRB;
    const uint32_t b4_koff   = (uint32_t)((lane >> 3) & 1) * 16;
    const uint32_t v4_rowoff = (uint32_t)(lane & 15) * ASTRB;
    const uint32_t v4_coloff = (uint32_t)((lane >> 4) & 1) * 16;

    const int qg0 = q0 + wid * 16 + g;
    const size_t bias_row0 = ((size_t)h * S_ + qg0) * S_ + 2 * tig;
    const size_t bias_row1 = bias_row0 + 8 * S_;

    constexpr int NT = S_ / 64;   // 32
    for (int kt = 0; kt < NT; kt++) {
        const int k0 = kt * 64;
        if (kt < NT - 1) { CP_WAIT1(); } else { CP_WAIT0(); }
        __syncthreads();
        if (kt + 2 < NT) {
            issue_kv(kt + 2, (kt + 2) % 3);
            CP_COMMIT();
        }

        const uint32_t sk = su + SKV + (kt % 3) * KVBUF;
        const uint32_t sv = sk + KTILE;

        // ---- S = Q'·K^T (f16, fp32 accum); K tiles pairwise via x4 ----
        float c[8][4];
        #pragma unroll
        for (int j = 0; j < 8; j++)
            #pragma unroll
            for (int r = 0; r < 4; r++) c[j][r] = 0.0f;

        #pragma unroll
        for (int ks = 0; ks < 4; ks++) {
            const uint32_t kb = ks * 32;
            uint32_t aq[4];
            ldsm_x4(aq, su + SQ + a_rowoff + kb + a_koff);
            #pragma unroll
            for (int jj = 0; jj < 4; jj++) {
                uint32_t bk4[4];
                ldsm_x4(bk4, sk + (uint32_t)(jj * 16) * ASTRB +
                             b4_rowoff + kb + b4_koff);
                mma_f16(c[2 * jj],     aq, &bk4[0]);
                mma_f16(c[2 * jj + 1], aq, &bk4[2]);
            }
        }

        // ---- P = ex2(c + bias*L2E + maskoff); fixed-max, no rescale ----
        uint32_t ap[4][4];
        #pragma unroll
        for (int j = 0; j < 8; j++) {
            const float2 mk = *(const float2*)&maskf[b * S_ + k0 + j * 8 + 2 * tig];
            const float2 b0 = *(const float2*)&bias[bias_row0 + k0 + j * 8];
            const float2 b1 = *(const float2*)&bias[bias_row1 + k0 + j * 8];
            c[j][0] = ex2f(fmaf(b0.x, L2E_, c[j][0]) + mk.x);
            c[j][1] = ex2f(fmaf(b0.y, L2E_, c[j][1]) + mk.y);
            c[j][2] = ex2f(fmaf(b1.x, L2E_, c[j][2]) + mk.x);
            c[j][3] = ex2f(fmaf(b1.y, L2E_, c[j][3]) + mk.y);
        }

        #pragma unroll
        for (int t = 0; t < 4; t++) {
            __half2 h0 = __floats2half2_rn(c[2 * t][0], c[2 * t][1]);
            __half2 h1 = __floats2half2_rn(c[2 * t][2], c[2 * t][3]);
            __half2 h2 = __floats2half2_rn(c[2 * t + 1][0], c[2 * t + 1][1]);
            __half2 h3 = __floats2half2_rn(c[2 * t + 1][2], c[2 * t + 1][3]);
            ap[t][0] = *(uint32_t*)&h0;
            ap[t][1] = *(uint32_t*)&h1;
            ap[t][2] = *(uint32_t*)&h2;
            ap[t][3] = *(uint32_t*)&h3;
        }

        // ---- ctx += P·V; l += P·1 (ones-operand MMA, exact fp32) ----
        #pragma unroll
        for (int t = 0; t < 4; t++) {
            const uint32_t vbase = sv + (uint32_t)(t * 16) * ASTRB +
                                   v4_rowoff + v4_coloff;
            #pragma unroll
            for (int jd = 0; jd < 8; jd += 2) {
                uint32_t bv4[4];
                ldsm_x4_trans(bv4, vbase + jd * 16);
                mma_f16(ctx[jd],     ap[t], &bv4[0]);
                mma_f16(ctx[jd + 1], ap[t], &bv4[2]);
            }
            mma_f16(cl, ap[t], bones);
        }
    }

    // cl[0]/cl[2] are row sums, identical across the quad (all ones cols).
    const float inv0 = 1.0f / fmaxf(cl[0], 1e-30f);
    const float inv1 = 1.0f / fmaxf(cl[2], 1e-30f);

    const size_t orow0 = ((size_t)(b * S_ + qg0)) * H_ + h * HD_ + 2 * tig;
    const size_t orow1 = orow0 + 8 * H_;
    #pragma unroll
    for (int jd = 0; jd < 8; jd++) {
        *(__half2*)&ctxo[orow0 + jd * 8] =
            __floats2half2_rn(ctx[jd][0] * inv0, ctx[jd][1] * inv0);
        *(__half2*)&ctxo[orow1 + jd * 8] =
            __floats2half2_rn(ctx[jd][2] * inv1, ctx[jd][3] * inv1);
    }
}

// ---------------------------------------------------------------------------
// Launch
// ---------------------------------------------------------------------------
extern "C" void kernel_launch(void* const* d_in, const int* in_sizes, int n_in,
                              void* d_out, int out_size)
{
    (void)in_sizes; (void)n_in; (void)out_size;

    const float* query = (const float*)d_in[0];
    const float* key_t = (const float*)d_in[1];
    const float* value = (const float*)d_in[2];
    const unsigned int* kpm_raw = (const unsigned int*)d_in[3];
    const float* bias  = (const float*)d_in[4];
    const float* q_w = (const float*)d_in[5];
    const float* q_b = (const float*)d_in[6];
    const float* k_w = (const float*)d_in[7];
    const float* k_b = (const float*)d_in[8];
    const float* v_w = (const float*)d_in[9];
    const float* v_b = (const float*)d_in[10];
    const float* o_w = (const float*)d_in[11];
    const float* o_b = (const float*)d_in[12];
    float* out = (float*)d_out;

    float* gmaskf;
    __half *gqh, *gkh, *gvh, *gch;
    cudaGetSymbolAddress((void**)&gmaskf, g_maskf);
    cudaGetSymbolAddress((void**)&gqh, g_qh);
    cudaGetSymbolAddress((void**)&gkh, g_kh);
    cudaGetSymbolAddress((void**)&gvh, g_vh);
    cudaGetSymbolAddress((void**)&gch, g_ch);

    cudaFuncSetAttribute(gemm_qkv,
                         cudaFuncAttributeMaxDynamicSharedMemorySize, GEMM_SMEM);
    cudaFuncSetAttribute(gemm_oproj,
                         cudaFuncAttributeMaxDynamicSharedMemorySize, GEMM_SMEM);
    cudaFuncSetAttribute(attn_f16,
                         cudaFuncAttributeMaxDynamicSharedMemorySize, ATTN_SMEM);

    mask_normalize<<<1, 1024>>>(kpm_raw);
    convert_all<<<16384, 256>>>(query, key_t, value, q_w, k_w, v_w, o_w);

    // Fused Q/K/V projections: grid (8, 32, 3)
    gemm_qkv<<<dim3(H_ / 128, M_ / 128, 3), 256, GEMM_SMEM>>>(q_b, k_b, v_b);

    // Grid (B, NH, S/128): batch pairs adjacent -> bias read hits L2 on 2nd
    attn_f16<<<dim3(B_, NH_, S_ / 128), 256, ATTN_SMEM>>>(
        gqh, gkh, gvh, gmaskf, bias, gch);

    // Output projection (ctx f16 from attention epilogue) -> fp32 out
    gemm_oproj<<<dim3(H_ / 128, M_ / 128), 256, GEMM_SMEM>>>(o_b, out);
}